// round 2
// baseline (speedup 1.0000x reference)
#include <cuda_runtime.h>
#include <math.h>

// Problem constants
constexpr int Cd  = 256;   // channels
constexpr int Hd  = 8;     // heads
constexpr int Ld  = 4;     // levels
constexpr int Pd  = 4;     // points
constexpr int LQd = 2048;  // queries
constexpr int LXd = 300;   // add keys

// Scratch (device globals; no allocation allowed)
__device__ float g_off[LQd * Cd];
__device__ int   g_lin[LQd * Hd * Ld * Pd];
__device__ float g_qw[LQd * Hd * Cd];           // [q][h][e]  (Wadd projections)
__device__ float g_slog[LQd * Hd * 16];         // scrambled attn_s logits [q][h][l*4+p]
__device__ float g_attn_a[LQd * Hd * LXd];      // [q][h][x] logits -> softmaxed weights
__device__ float g_agg[LQd * Hd * Cd];          // [q][h][e] attention-weighted key sums
__device__ float g_ssum[LQd * Hd];
__device__ float g_headw[(Hd + 1) * Cd];        // [j][c]
__device__ float g_wv0ft[Hd * Cd * Cd];         // [h][e][c] folded
__device__ float g_bv0f[Hd * Cd];               // [h][c] folded
__device__ float g_v2f[Hd * LXd * Cd];          // [h][x][c] folded

// ---------------------------------------------------------------------------
// Tiled fp32 GEMM: C = A @ B (or A @ B^T if TB), optional accumulate.
// BM=BN=64, BK=16, 256 threads, 4x4 micro-tile per thread. K % 16 == 0.
// ---------------------------------------------------------------------------
template <bool TB>
__global__ void sgemm(const float* __restrict__ A, int lda, long sA,
                      const float* __restrict__ B, int ldb, long sB,
                      float* __restrict__ Cm, int ldc, long sC,
                      int M, int N, int K, int accum)
{
    __shared__ float As[16][68];
    __shared__ float Bs[16][68];
    const int tid = threadIdx.x;
    const int bx = blockIdx.x, by = blockIdx.y, bz = blockIdx.z;
    A  += (long)bz * sA;
    B  += (long)bz * sB;
    Cm += (long)bz * sC;
    const int rowBase = by * 64, colBase = bx * 64;
    const int tr = (tid >> 4) * 4, tc = (tid & 15) * 4;
    float acc[4][4] = {};

    for (int kt = 0; kt < K; kt += 16) {
#pragma unroll
        for (int i = 0; i < 4; i++) {
            int idx = tid + i * 256;
            int ar = idx >> 4, ac = idx & 15;
            int gr = rowBase + ar;
            As[ac][ar] = (gr < M) ? A[(long)gr * lda + kt + ac] : 0.f;
        }
        if (TB) {
#pragma unroll
            for (int i = 0; i < 4; i++) {
                int idx = tid + i * 256;
                int bn = idx >> 4, bk = idx & 15;
                int gn = colBase + bn;
                Bs[bk][bn] = (gn < N) ? B[(long)gn * ldb + kt + bk] : 0.f;
            }
        } else {
#pragma unroll
            for (int i = 0; i < 4; i++) {
                int idx = tid + i * 256;
                int bk = idx >> 6, bn = idx & 63;
                int gn = colBase + bn;
                Bs[bk][bn] = (gn < N) ? B[(long)(kt + bk) * ldb + gn] : 0.f;
            }
        }
        __syncthreads();
#pragma unroll
        for (int k = 0; k < 16; k++) {
            float4 av = *(const float4*)&As[k][tr];
            float4 bv = *(const float4*)&Bs[k][tc];
            float a[4] = {av.x, av.y, av.z, av.w};
            float b[4] = {bv.x, bv.y, bv.z, bv.w};
#pragma unroll
            for (int i = 0; i < 4; i++)
#pragma unroll
                for (int j = 0; j < 4; j++) acc[i][j] += a[i] * b[j];
        }
        __syncthreads();
    }
#pragma unroll
    for (int i = 0; i < 4; i++) {
        int gr = rowBase + tr + i;
        if (gr >= M) continue;
#pragma unroll
        for (int j = 0; j < 4; j++) {
            int gc = colBase + tc + j;
            if (gc < N) {
                long o = (long)gr * ldc + gc;
                if (accum) Cm[o] += acc[i][j];
                else       Cm[o] = acc[i][j];
            }
        }
    }
}

// ---------------------------------------------------------------------------
// Prep: head_w = softmax(W_mix^T, axis=0); fold bv0.
// ---------------------------------------------------------------------------
__global__ void prep_headw(const float* __restrict__ W_mix, const float* __restrict__ b_v)
{
    int c = threadIdx.x;
    float m = -1e30f;
    for (int j = 0; j <= Hd; j++) m = fmaxf(m, W_mix[c * (Hd + 1) + j]);
    float e[Hd + 1];
    float Z = 0.f;
    for (int j = 0; j <= Hd; j++) { e[j] = expf(W_mix[c * (Hd + 1) + j] - m); Z += e[j]; }
    float invZ = 1.f / Z;
    for (int j = 0; j <= Hd; j++) g_headw[j * Cd + c] = e[j] * invZ;
    for (int h = 0; h < Hd; h++)  g_bv0f[h * Cd + c] = e[h] * invZ * b_v[(2 * h) * Cd + c];
}

// Fold + transpose Wv0: g_wv0ft[h][e][c] = head_w[h][c] * W_v[2h][c][e]
__global__ void prep_fold(const float* __restrict__ W_v)
{
    __shared__ float t[32][33];
    int h = blockIdx.z;
    int e0 = blockIdx.x * 32, c0 = blockIdx.y * 32;
    int x = threadIdx.x, y = threadIdx.y;
    for (int i = 0; i < 32; i += 8) {
        int cc = c0 + y + i;
        t[y + i][x] = W_v[((long)(2 * h) * Cd + cc) * Cd + e0 + x];
    }
    __syncthreads();
    for (int i = 0; i < 32; i += 8) {
        int ee = e0 + y + i;
        int cc = c0 + x;
        g_wv0ft[((long)h * Cd + ee) * Cd + cc] = g_headw[h * Cd + cc] * t[x][y + i];
    }
}

// g_v2f[h][x][c] = head_w[h][c] * (raw_v2[h][x][c] + b_v[2h+1][c])
__global__ void fold_v2f(const float* __restrict__ b_v)
{
    int i = blockIdx.x * 256 + threadIdx.x;
    int c = i & 255;
    int h = (i >> 8) / LXd;
    g_v2f[i] = g_headw[h * Cd + c] * (g_v2f[i] + b_v[(2 * h + 1) * Cd + c]);
}

// ---------------------------------------------------------------------------
// Sampling locations -> linear gather indices
// ---------------------------------------------------------------------------
__global__ void loc_kernel(const float* __restrict__ ref, const float* __restrict__ b_off,
                           const int* __restrict__ iss, const int* __restrict__ lsi)
{
    int id = blockIdx.x * 256 + threadIdx.x;           // q*128 + h*16 + l*4 + p
    if (id >= LQd * Hd * Ld * Pd) return;
    int q = id >> 7;
    int r = id & 127;
    int hh = r >> 4;
    int l = (r >> 2) & 3;
    int p = r & 3;
    int j = ((hh * Ld + l) * Pd + p) * 2;
    float off0 = g_off[q * Cd + j]     + b_off[j];
    float off1 = g_off[q * Cd + j + 1] + b_off[j + 1];
    int W0 = iss[l * 2], W1 = iss[l * 2 + 1];
    float ref0 = ref[(q * Ld + l) * 2];
    float ref1 = ref[(q * Ld + l) * 2 + 1];
    // wh = iss[:, ::-1]
    float loc0 = ref0 + off0 / (float)W1;
    float loc1 = ref1 + off1 / (float)W0;
    loc0 = fminf(fmaxf(loc0, 0.f), 0.999f);
    loc1 = fminf(fmaxf(loc1, 0.f), 0.999f);
    int ix = (int)(loc0 * (float)W0);
    int iy = (int)(loc1 * (float)W1);
    g_lin[id] = ix + iy * W0 + lsi[l];
}

// ---------------------------------------------------------------------------
// Scrambled attn_s logits.
// attn_s[h,l,p,q] = sum_c' qf[q,c'] * sum_e Ws[h,l, p*64+q/32, e]
//                        * keys[h,l, (q%32)/8, 256*(q%8)+c', e]
// Block (r=q%32, l, h): M[j,e] = sum_c' qf[r+32j,c'] * K[c',e]  (64x256x256 GEMM)
// then logit[p,j] = Ws[h,l,p*64+j,:] . M[j,:]
// ---------------------------------------------------------------------------
__global__ void slog_kernel(const float* __restrict__ flat,
                            const float* __restrict__ query,
                            const float* __restrict__ W_attn)
{
    __shared__ float As[16][68];    // As[kc][j] = qf[r+32j, ck+kc]
    __shared__ float Bs[16][260];   // Bs[kc][e] = K[ck+kc, e]
    __shared__ int   slin[256];
    extern __shared__ float Ms[];   // [64][257]

    const int r = blockIdx.x, l = blockIdx.y, h = blockIdx.z;
    const int tid = threadIdx.x;
    const int p2 = r >> 3, b = r & 7;

    {   // gather rows: c' -> flat row index
        int q2 = 256 * b + tid;
        slin[tid] = g_lin[(q2 * Hd + h) * 16 + l * 4 + p2];
    }
    __syncthreads();

    const int tr = tid >> 4, tc = tid & 15;   // rows tr*4..+3; cols tc*4 + 64g + u
    float acc[4][4][4] = {};

    for (int ck = 0; ck < 256; ck += 16) {
#pragma unroll
        for (int i = 0; i < 4; i++) {
            int idx = tid + i * 256;
            int kc = idx & 15, j = idx >> 4;
            As[kc][j] = query[(r + 32 * j) * Cd + ck + kc];
        }
#pragma unroll
        for (int i = 0; i < 4; i++) {
            int idx = tid + i * 256;     // float4 slots
            int kc = idx >> 6;
            int e4 = idx & 63;
            float4 v = *(const float4*)&flat[(long)slin[ck + kc] * Cd + e4 * 4];
            *(float4*)&Bs[kc][e4 * 4] = v;
        }
        __syncthreads();
#pragma unroll
        for (int kc = 0; kc < 16; kc++) {
            float4 av = *(const float4*)&As[kc][tr * 4];
            float a[4] = {av.x, av.y, av.z, av.w};
#pragma unroll
            for (int g = 0; g < 4; g++) {
                float4 bv = *(const float4*)&Bs[kc][tc * 4 + 64 * g];
                float bb[4] = {bv.x, bv.y, bv.z, bv.w};
#pragma unroll
                for (int i = 0; i < 4; i++)
#pragma unroll
                    for (int u = 0; u < 4; u++)
                        acc[i][g][u] += a[i] * bb[u];
            }
        }
        __syncthreads();
    }

    // store M into dynamic shared (pitch 257 => conflict-free row access)
#pragma unroll
    for (int i = 0; i < 4; i++)
#pragma unroll
        for (int g = 0; g < 4; g++)
#pragma unroll
            for (int u = 0; u < 4; u++)
                Ms[(tr * 4 + i) * 257 + tc * 4 + 64 * g + u] = acc[i][g][u];
    __syncthreads();

    // one logit per thread
    int p = tid >> 6, j = tid & 63;
    int cstar = p * 64 + j;
    const float4* w4 = (const float4*)(W_attn + ((long)(h * Ld + l) * Cd + cstar) * Cd);
    const float* mrow = &Ms[j * 257];
    float s = 0.f;
#pragma unroll 4
    for (int e4 = 0; e4 < 64; e4++) {
        float4 w = w4[e4];
        s += w.x * mrow[e4 * 4] + w.y * mrow[e4 * 4 + 1]
           + w.z * mrow[e4 * 4 + 2] + w.w * mrow[e4 * 4 + 3];
    }
    int q = r + 32 * j;
    g_slog[(q * Hd + h) * 16 + l * 4 + p] = s;
}

// ---------------------------------------------------------------------------
// Fused: gather 16 keys, softmax over 16+300, agg_s, normalized attn_a
// weights written back in-place. One block per (q,h).
// ---------------------------------------------------------------------------
__global__ void fuse_kernel(const float* __restrict__ flat)
{
    __shared__ float skeys[16][Cd];
    __shared__ int   slin[16];
    __shared__ float slog[16];
    __shared__ float sws[16];
    __shared__ float red[8];
    __shared__ float sm_max, sm_sum;

    const int q = blockIdx.x, h = blockIdx.y, t = threadIdx.x;
    const int warp = t >> 5, lane = t & 31;

    if (t < 16) {
        slin[t] = g_lin[(q * Hd + h) * 16 + t];
        slog[t] = g_slog[(q * Hd + h) * 16 + t];
    }
    __syncthreads();
#pragma unroll
    for (int k = 0; k < 16; k++)
        skeys[k][t] = flat[(long)slin[k] * Cd + t];

    const int row = (q * Hd + h) * LXd;
    float la0 = g_attn_a[row + t];                              // t < 256 <= 300
    float la1 = (t < LXd - 256) ? g_attn_a[row + 256 + t] : -1e30f;

    // block max over 316 logits
    float m = fmaxf(la0, la1);
    if (t < 16) m = fmaxf(m, slog[t]);
#pragma unroll
    for (int o = 16; o > 0; o >>= 1) m = fmaxf(m, __shfl_xor_sync(0xffffffffu, m, o));
    if (lane == 0) red[warp] = m;
    __syncthreads();
    if (t == 0) {
        float mm = red[0];
        for (int w = 1; w < 8; w++) mm = fmaxf(mm, red[w]);
        sm_max = mm;
    }
    __syncthreads();
    m = sm_max;

    float e0 = expf(la0 - m);
    float e1 = (t < LXd - 256) ? expf(la1 - m) : 0.f;
    float es = (t < 16) ? expf(slog[t] - m) : 0.f;
    float csum = e0 + e1 + es;
#pragma unroll
    for (int o = 16; o > 0; o >>= 1) csum += __shfl_xor_sync(0xffffffffu, csum, o);
    if (lane == 0) red[warp] = csum;
    __syncthreads();
    if (t == 0) {
        float s2 = 0.f;
        for (int w = 0; w < 8; w++) s2 += red[w];
        sm_sum = s2;
    }
    __syncthreads();
    const float invZ = 1.f / sm_sum;

    g_attn_a[row + t] = e0 * invZ;
    if (t < LXd - 256) g_attn_a[row + 256 + t] = e1 * invZ;
    if (t < 16) sws[t] = es * invZ;
    if (warp == 0) {
        float ss = (t < 16) ? es * invZ : 0.f;
#pragma unroll
        for (int o = 16; o > 0; o >>= 1) ss += __shfl_xor_sync(0xffffffffu, ss, o);
        if (t == 0) g_ssum[q * Hd + h] = ss;
    }
    __syncthreads();

    float a = 0.f;
#pragma unroll
    for (int k = 0; k < 16; k++) a += sws[k] * skeys[k][t];
    g_agg[((long)q * Hd + h) * Cd + t] = a;
}

// d_out init: qf*head_w[-1] + sum_h s_sum*bv0f (GEMMs accumulate on top)
__global__ void init_out(const float* __restrict__ query, float* __restrict__ out)
{
    int i = blockIdx.x * 256 + threadIdx.x;
    int c = i & 255, q = i >> 8;
    float v = query[i] * g_headw[Hd * Cd + c];
#pragma unroll
    for (int h = 0; h < Hd; h++) v += g_ssum[q * Hd + h] * g_bv0f[h * Cd + c];
    out[i] = v;
}

// ---------------------------------------------------------------------------
extern "C" void kernel_launch(void* const* d_in, const int* in_sizes, int n_in,
                              void* d_out, int out_size)
{
    const float* query  = (const float*)d_in[0];
    const float* ref    = (const float*)d_in[1];
    const float* flat   = (const float*)d_in[2];
    const int*   iss    = (const int*)  d_in[3];
    const float* ak     = (const float*)d_in[4];
    const int*   lsi    = (const int*)  d_in[5];
    const float* W_off  = (const float*)d_in[6];
    const float* b_off  = (const float*)d_in[7];
    const float* W_attn = (const float*)d_in[8];
    const float* W_v    = (const float*)d_in[9];
    const float* b_v    = (const float*)d_in[10];
    const float* W_mix  = (const float*)d_in[11];
    float* out = (float*)d_out;

    float *p_off, *p_qw, *p_attn_a, *p_agg, *p_v2f, *p_wv0ft;
    cudaGetSymbolAddress((void**)&p_off,    g_off);
    cudaGetSymbolAddress((void**)&p_qw,     g_qw);
    cudaGetSymbolAddress((void**)&p_attn_a, g_attn_a);
    cudaGetSymbolAddress((void**)&p_agg,    g_agg);
    cudaGetSymbolAddress((void**)&p_v2f,    g_v2f);
    cudaGetSymbolAddress((void**)&p_wv0ft,  g_wv0ft);

    static int smem_set = 0;
    const int slog_smem = 64 * 257 * 4;
    if (!smem_set) {
        cudaFuncSetAttribute(slog_kernel,
                             cudaFuncAttributeMaxDynamicSharedMemorySize, slog_smem);
        smem_set = 1;
    }

    // head mixing weights + folds
    prep_headw<<<1, 256>>>(W_mix, b_v);
    prep_fold<<<dim3(8, 8, Hd), dim3(32, 8)>>>(W_v);

    // raw v2[h] = ak @ Wv1[h]^T  (batched, TB)
    sgemm<true><<<dim3((Cd + 63) / 64, (LXd + 63) / 64, Hd), 256>>>(
        ak, Cd, 0L, W_v + (long)Cd * Cd, Cd, 2L * Cd * Cd,
        p_v2f, Cd, (long)LXd * Cd, LXd, Cd, Cd, 0);
    fold_v2f<<<Hd * LXd, 256>>>(b_v);

    // off = query @ W_off^T
    sgemm<true><<<dim3(4, 32, 1), 256>>>(
        query, Cd, 0L, W_off, Cd, 0L, p_off, Cd, 0L, LQd, Cd, Cd, 0);
    loc_kernel<<<(LQd * Hd * Ld * Pd + 255) / 256, 256>>>(ref, b_off, iss, lsi);

    // qwadd[h] = query @ W_attn[4h+4]  (batched over h)
    sgemm<false><<<dim3(4, 32, Hd), 256>>>(
        query, Cd, 0L, W_attn + 4L * Cd * Cd, Cd, 4L * Cd * Cd,
        p_qw, Hd * Cd, (long)Cd, LQd, Cd, Cd, 0);

    // attn_a logits[h] = qwadd[h] @ ak^T (batched, TB)
    sgemm<true><<<dim3((LXd + 63) / 64, 32, Hd), 256>>>(
        p_qw, Hd * Cd, (long)Cd, ak, Cd, 0L,
        p_attn_a, Hd * LXd, (long)LXd, LQd, LXd, Cd, 0);

    // scrambled attn_s logits
    slog_kernel<<<dim3(32, Ld, Hd), 256, slog_smem>>>(flat, query, W_attn);

    // gather + softmax + aggregation
    fuse_kernel<<<dim3(LQd, Hd), 256>>>(flat);

    // output: init, then two accumulating GEMMs
    init_out<<<LQd * Cd / 256, 256>>>(query, out);
    sgemm<false><<<dim3(4, 32, 1), 256>>>(
        p_agg, Hd * Cd, 0L, p_wv0ft, Cd, 0L, out, Cd, 0L, LQd, Cd, Hd * Cd, 1);
    sgemm<false><<<dim3(4, 32, 1), 256>>>(
        p_attn_a, Hd * LXd, 0L, p_v2f, Cd, 0L, out, Cd, 0L, LQd, Cd, Hd * LXd, 1);
}

// round 5
// speedup vs baseline: 1.3913x; 1.3913x over previous
#include <cuda_runtime.h>
#include <cuda_bf16.h>
#include <math.h>

// Problem constants
constexpr int Cd  = 256;
constexpr int Hd  = 8;
constexpr int Ld  = 4;
constexpr int Pd  = 4;
constexpr int LQd = 2048;
constexpr int LXd = 300;

// Scratch (device globals; no allocation allowed)
__device__ __align__(16) float g_off[LQd * Cd];
__device__ __align__(16) int   g_lin[LQd * Hd * Ld * Pd];
__device__ __align__(16) float g_P[Hd * Cd * LXd];         // [h][c][x]
__device__ __align__(16) float g_slog[LQd * Hd * 16];
__device__ __align__(16) float g_attn_a[LQd * Hd * LXd];   // [q][h][x]
__device__ __align__(16) float g_agg[LQd * Hd * Cd];       // [q][h][e]
__device__ __align__(16) float g_ssum[LQd * Hd];
__device__ __align__(16) float g_headw[(Hd + 1) * Cd];
__device__ __align__(16) float g_wv0ft[Hd * Cd * Cd];      // [h][e][c] folded
__device__ __align__(16) float g_bv0f[Hd * Cd];
__device__ __align__(16) float g_v2f[Hd * LXd * Cd];       // [h][x][c] folded
__device__ __align__(16) float g_part[4][LQd * Cd];        // split-K partials

// ---------------------------------------------------------------------------
// MMA helpers (bf16 hi/lo x3 emulated fp32)
// ---------------------------------------------------------------------------
__device__ __forceinline__ unsigned smem_u32(const void* p) {
    return (unsigned)__cvta_generic_to_shared(p);
}
__device__ __forceinline__ void ldsm_x4(unsigned addr, unsigned& r0, unsigned& r1,
                                        unsigned& r2, unsigned& r3) {
    asm volatile("ldmatrix.sync.aligned.m8n8.x4.shared.b16 {%0,%1,%2,%3}, [%4];"
                 : "=r"(r0), "=r"(r1), "=r"(r2), "=r"(r3) : "r"(addr));
}
__device__ __forceinline__ void ldsm_x4_trans(unsigned addr, unsigned& r0, unsigned& r1,
                                              unsigned& r2, unsigned& r3) {
    asm volatile("ldmatrix.sync.aligned.m8n8.x4.trans.shared.b16 {%0,%1,%2,%3}, [%4];"
                 : "=r"(r0), "=r"(r1), "=r"(r2), "=r"(r3) : "r"(addr));
}
__device__ __forceinline__ void mma_bf16(float* c, const unsigned* a,
                                         unsigned b0, unsigned b1) {
    asm volatile(
        "mma.sync.aligned.m16n8k16.row.col.f32.bf16.bf16.f32 "
        "{%0,%1,%2,%3},{%4,%5,%6,%7},{%8,%9},{%0,%1,%2,%3};"
        : "+f"(c[0]), "+f"(c[1]), "+f"(c[2]), "+f"(c[3])
        : "r"(a[0]), "r"(a[1]), "r"(a[2]), "r"(a[3]), "r"(b0), "r"(b1));
}
__device__ __forceinline__ void cvt4(float4 v, __nv_bfloat16* hp, __nv_bfloat16* lp) {
    float f[4] = {v.x, v.y, v.z, v.w};
    __nv_bfloat16 h[4], l[4];
#pragma unroll
    for (int e = 0; e < 4; e++) {
        h[e] = __float2bfloat16(f[e]);
        l[e] = __float2bfloat16(f[e] - __bfloat162float(h[e]));
    }
    *(__nv_bfloat162*)hp       = __halves2bfloat162(h[0], h[1]);
    *(__nv_bfloat162*)(hp + 2) = __halves2bfloat162(h[2], h[3]);
    *(__nv_bfloat162*)lp       = __halves2bfloat162(l[0], l[1]);
    *(__nv_bfloat162*)(lp + 2) = __halves2bfloat162(l[2], l[3]);
}

// ---------------------------------------------------------------------------
// Generic fp32-accuracy GEMM via bf16x3 MMA.  C = A[M,K-slice] @ B[K-slice,N]
// A row-major [M][lda], B row-major [K][ldb] (non-transposed), C row-major.
// BM=64, BN=64, BK=32, 256 threads, 8 warps (2m x 4n), warp tile 32x16.
// kOff/kLen select the K slice (both multiples of 32). Plain store (no accum).
// ---------------------------------------------------------------------------
__global__ __launch_bounds__(256) void gemm_mma(
    const float* __restrict__ A, int lda, long sA,
    const float* __restrict__ B, int ldb, long sB,
    float* __restrict__ Cm, int ldc, long sC,
    int M, int N, int kOff, int kLen)
{
    __shared__ __nv_bfloat16 Ah[64][40], Al[64][40];
    __shared__ __nv_bfloat16 Bh[32][72], Bl[32][72];
    const int tid = threadIdx.x, lane = tid & 31, warp = tid >> 5;
    const int wm = warp >> 2, wn = warp & 3;
    A  += (long)blockIdx.z * sA;
    B  += (long)blockIdx.z * sB;
    Cm += (long)blockIdx.z * sC;
    const int rowBase = blockIdx.y * 64, colBase = blockIdx.x * 64;

    float acc[2][2][4] = {};

    for (int kt = 0; kt < kLen; kt += 32) {
#pragma unroll
        for (int i = 0; i < 2; i++) {
            int idx = tid + i * 256;
            int r = idx >> 3, c4 = (idx & 7) * 4;
            int gr = rowBase + r;
            float4 v = make_float4(0.f, 0.f, 0.f, 0.f);
            if (gr < M) v = *(const float4*)&A[(long)gr * lda + kOff + kt + c4];
            cvt4(v, &Ah[r][c4], &Al[r][c4]);
        }
#pragma unroll
        for (int i = 0; i < 2; i++) {
            int idx = tid + i * 256;
            int kr = idx >> 4, nq = (idx & 15) * 4;
            int gn = colBase + nq;
            const float* Brow = &B[(long)(kOff + kt + kr) * ldb];
            float4 v;
            if (gn + 3 < N) v = *(const float4*)&Brow[gn];
            else {
                v.x = (gn     < N) ? Brow[gn]     : 0.f;
                v.y = (gn + 1 < N) ? Brow[gn + 1] : 0.f;
                v.z = (gn + 2 < N) ? Brow[gn + 2] : 0.f;
                v.w = (gn + 3 < N) ? Brow[gn + 3] : 0.f;
            }
            cvt4(v, &Bh[kr][nq], &Bl[kr][nq]);
        }
        __syncthreads();
#pragma unroll
        for (int kk = 0; kk < 32; kk += 16) {
            unsigned ah[2][4], al[2][4], bh[4], bl[4];
#pragma unroll
            for (int mi = 0; mi < 2; mi++) {
                int rr = wm * 32 + mi * 16 + (lane & 15);
                int cc = kk + (lane >> 4) * 8;
                ldsm_x4(smem_u32(&Ah[rr][cc]), ah[mi][0], ah[mi][1], ah[mi][2], ah[mi][3]);
                ldsm_x4(smem_u32(&Al[rr][cc]), al[mi][0], al[mi][1], al[mi][2], al[mi][3]);
            }
            {
                int rr = kk + (lane & 15);
                int cc = wn * 16 + (lane >> 4) * 8;
                ldsm_x4_trans(smem_u32(&Bh[rr][cc]), bh[0], bh[1], bh[2], bh[3]);
                ldsm_x4_trans(smem_u32(&Bl[rr][cc]), bl[0], bl[1], bl[2], bl[3]);
            }
#pragma unroll
            for (int mi = 0; mi < 2; mi++)
#pragma unroll
                for (int ni = 0; ni < 2; ni++) {
                    mma_bf16(acc[mi][ni], ah[mi], bh[ni * 2], bh[ni * 2 + 1]);
                    mma_bf16(acc[mi][ni], ah[mi], bl[ni * 2], bl[ni * 2 + 1]);
                    mma_bf16(acc[mi][ni], al[mi], bh[ni * 2], bh[ni * 2 + 1]);
                }
        }
        __syncthreads();
    }

    const int g = lane >> 2, qp = lane & 3;
#pragma unroll
    for (int mi = 0; mi < 2; mi++)
#pragma unroll
        for (int ni = 0; ni < 2; ni++)
#pragma unroll
            for (int ch = 0; ch < 2; ch++) {
                int gr = rowBase + wm * 32 + mi * 16 + g + ch * 8;
                int gc = colBase + wn * 16 + ni * 8 + qp * 2;
                if (gr < M && gc < N)
                    *(float2*)&Cm[(long)gr * ldc + gc] =
                        make_float2(acc[mi][ni][ch * 2], acc[mi][ni][ch * 2 + 1]);
            }
}

// ---------------------------------------------------------------------------
// Scrambled attn_s logits via bf16x3 MMA.
// Block (r,l,h): M[j,e] = sum_c' qf[r+32j,c'] * flat[slin[c']][e]   (64x256x256)
// then logit[p,j] = Ws[h,l,p*64+j,:] . M[j,:]
// ---------------------------------------------------------------------------
__global__ __launch_bounds__(256) void slog_mma(
    const float* __restrict__ flat, const float* __restrict__ query,
    const float* __restrict__ W_attn)
{
    extern __shared__ float sm[];
    float* Ms = sm;                                          // [64][268]
    __nv_bfloat16* Ah = (__nv_bfloat16*)(sm + 64 * 268);     // [64][40]
    __nv_bfloat16* Al = Ah + 64 * 40;
    __nv_bfloat16* Bh = Al + 64 * 40;                        // [32][264]
    __nv_bfloat16* Bl = Bh + 32 * 264;
    __shared__ int slin[256];

    const int r = blockIdx.x, l = blockIdx.y, h = blockIdx.z;
    const int tid = threadIdx.x, lane = tid & 31, warp = tid >> 5;
    const int wm = warp & 1, wn = warp >> 1;                 // m0=wm*32, n0=wn*64
    const int p2 = r >> 3, b = r & 7;
    slin[tid] = g_lin[((256 * b + tid) * Hd + h) * 16 + l * 4 + p2];
    __syncthreads();

    float acc[2][8][4] = {};

    for (int ck = 0; ck < 256; ck += 32) {
#pragma unroll
        for (int i = 0; i < 2; i++) {
            int idx = tid + i * 256;
            int j = idx >> 3, c4 = (idx & 7) * 4;
            float4 v = *(const float4*)&query[(r + 32 * j) * Cd + ck + c4];
            cvt4(v, Ah + j * 40 + c4, Al + j * 40 + c4);
        }
#pragma unroll
        for (int i = 0; i < 8; i++) {
            int idx = tid + i * 256;
            int kr = idx >> 6, c4 = (idx & 63) * 4;
            float4 v = *(const float4*)&flat[(long)slin[ck + kr] * Cd + c4];
            cvt4(v, Bh + kr * 264 + c4, Bl + kr * 264 + c4);
        }
        __syncthreads();
#pragma unroll
        for (int kk = 0; kk < 32; kk += 16) {
            unsigned ah[2][4], al[2][4];
#pragma unroll
            for (int mi = 0; mi < 2; mi++) {
                int rr = wm * 32 + mi * 16 + (lane & 15);
                int cc = kk + (lane >> 4) * 8;
                ldsm_x4(smem_u32(Ah + rr * 40 + cc), ah[mi][0], ah[mi][1], ah[mi][2], ah[mi][3]);
                ldsm_x4(smem_u32(Al + rr * 40 + cc), al[mi][0], al[mi][1], al[mi][2], al[mi][3]);
            }
#pragma unroll
            for (int nb = 0; nb < 4; nb++) {
                unsigned bh[4], bl[4];
                int rr = kk + (lane & 15);
                int cc = wn * 64 + nb * 16 + (lane >> 4) * 8;
                ldsm_x4_trans(smem_u32(Bh + rr * 264 + cc), bh[0], bh[1], bh[2], bh[3]);
                ldsm_x4_trans(smem_u32(Bl + rr * 264 + cc), bl[0], bl[1], bl[2], bl[3]);
#pragma unroll
                for (int mi = 0; mi < 2; mi++)
#pragma unroll
                    for (int t = 0; t < 2; t++) {
                        int ni = nb * 2 + t;
                        mma_bf16(acc[mi][ni], ah[mi], bh[t * 2], bh[t * 2 + 1]);
                        mma_bf16(acc[mi][ni], ah[mi], bl[t * 2], bl[t * 2 + 1]);
                        mma_bf16(acc[mi][ni], al[mi], bh[t * 2], bh[t * 2 + 1]);
                    }
            }
        }
        __syncthreads();
    }

    // acc -> Ms (pitch 268 -> conflict-spread rows)
    const int g = lane >> 2, qp = lane & 3;
#pragma unroll
    for (int mi = 0; mi < 2; mi++)
#pragma unroll
        for (int ni = 0; ni < 8; ni++)
#pragma unroll
            for (int ch = 0; ch < 2; ch++) {
                int row = wm * 32 + mi * 16 + g + ch * 8;
                int col = wn * 64 + ni * 8 + qp * 2;
                *(float2*)&Ms[row * 268 + col] =
                    make_float2(acc[mi][ni][ch * 2], acc[mi][ni][ch * 2 + 1]);
            }
    __syncthreads();

    // stage 2: one logit per thread
    int p = tid >> 6, j = tid & 63;
    int cstar = p * 64 + j;
    const float4* w4 = (const float4*)(W_attn + ((long)(h * Ld + l) * Cd + cstar) * Cd);
    const float* mrow = Ms + j * 268;
    float s = 0.f;
#pragma unroll 4
    for (int e4 = 0; e4 < 64; e4++) {
        float4 w = w4[e4];
        s += w.x * mrow[e4 * 4] + w.y * mrow[e4 * 4 + 1]
           + w.z * mrow[e4 * 4 + 2] + w.w * mrow[e4 * 4 + 3];
    }
    int q = r + 32 * j;
    g_slog[(q * Hd + h) * 16 + l * 4 + p] = s;
}

// ---------------------------------------------------------------------------
// fp32 tiled GEMM (TB): C = A @ B^T  (small prep GEMMs only)
// ---------------------------------------------------------------------------
__global__ void sgemm_tb(const float* __restrict__ A, int lda, long sA,
                         const float* __restrict__ B, int ldb, long sB,
                         float* __restrict__ Cm, int ldc, long sC,
                         int M, int N, int K)
{
    __shared__ float As[16][68];
    __shared__ float Bs[16][68];
    const int tid = threadIdx.x;
    A  += (long)blockIdx.z * sA;
    B  += (long)blockIdx.z * sB;
    Cm += (long)blockIdx.z * sC;
    const int rowBase = blockIdx.y * 64, colBase = blockIdx.x * 64;
    const int tr = (tid >> 4) * 4, tc = (tid & 15) * 4;
    float acc[4][4] = {};

    for (int kt = 0; kt < K; kt += 16) {
#pragma unroll
        for (int i = 0; i < 4; i++) {
            int idx = tid + i * 256;
            int ar = idx >> 4, ac = idx & 15;
            int gr = rowBase + ar;
            As[ac][ar] = (gr < M) ? A[(long)gr * lda + kt + ac] : 0.f;
        }
#pragma unroll
        for (int i = 0; i < 4; i++) {
            int idx = tid + i * 256;
            int bn = idx >> 4, bk = idx & 15;
            int gn = colBase + bn;
            Bs[bk][bn] = (gn < N) ? B[(long)gn * ldb + kt + bk] : 0.f;
        }
        __syncthreads();
#pragma unroll
        for (int k = 0; k < 16; k++) {
            float4 av = *(const float4*)&As[k][tr];
            float4 bv = *(const float4*)&Bs[k][tc];
            float a[4] = {av.x, av.y, av.z, av.w};
            float b[4] = {bv.x, bv.y, bv.z, bv.w};
#pragma unroll
            for (int i = 0; i < 4; i++)
#pragma unroll
                for (int j = 0; j < 4; j++) acc[i][j] += a[i] * b[j];
        }
        __syncthreads();
    }
#pragma unroll
    for (int i = 0; i < 4; i++) {
        int gr = rowBase + tr + i;
        if (gr >= M) continue;
#pragma unroll
        for (int j = 0; j < 4; j++) {
            int gc = colBase + tc + j;
            if (gc < N) Cm[(long)gr * ldc + gc] = acc[i][j];
        }
    }
}

// ---------------------------------------------------------------------------
// Prep kernels
// ---------------------------------------------------------------------------
__global__ void prep_headw(const float* __restrict__ W_mix, const float* __restrict__ b_v)
{
    int c = threadIdx.x;
    float m = -1e30f;
    for (int j = 0; j <= Hd; j++) m = fmaxf(m, W_mix[c * (Hd + 1) + j]);
    float e[Hd + 1];
    float Z = 0.f;
    for (int j = 0; j <= Hd; j++) { e[j] = expf(W_mix[c * (Hd + 1) + j] - m); Z += e[j]; }
    float invZ = 1.f / Z;
    for (int j = 0; j <= Hd; j++) g_headw[j * Cd + c] = e[j] * invZ;
    for (int h = 0; h < Hd; h++)  g_bv0f[h * Cd + c] = e[h] * invZ * b_v[(2 * h) * Cd + c];
}

__global__ void prep_fold(const float* __restrict__ W_v)
{
    __shared__ float t[32][33];
    int h = blockIdx.z;
    int e0 = blockIdx.x * 32, c0 = blockIdx.y * 32;
    int x = threadIdx.x, y = threadIdx.y;
    for (int i = 0; i < 32; i += 8) {
        int cc = c0 + y + i;
        t[y + i][x] = W_v[((long)(2 * h) * Cd + cc) * Cd + e0 + x];
    }
    __syncthreads();
    for (int i = 0; i < 32; i += 8) {
        int ee = e0 + y + i;
        int cc = c0 + x;
        g_wv0ft[((long)h * Cd + ee) * Cd + cc] = g_headw[h * Cd + cc] * t[x][y + i];
    }
}

__global__ void fold_v2f(const float* __restrict__ b_v)
{
    int i = blockIdx.x * 256 + threadIdx.x;
    int c = i & 255;
    int h = (i >> 8) / LXd;
    g_v2f[i] = g_headw[h * Cd + c] * (g_v2f[i] + b_v[(2 * h + 1) * Cd + c]);
}

__global__ void loc_kernel(const float* __restrict__ ref, const float* __restrict__ b_off,
                           const int* __restrict__ iss, const int* __restrict__ lsi)
{
    int id = blockIdx.x * 256 + threadIdx.x;
    if (id >= LQd * Hd * Ld * Pd) return;
    int q = id >> 7;
    int r = id & 127;
    int hh = r >> 4;
    int l = (r >> 2) & 3;
    int p = r & 3;
    int j = ((hh * Ld + l) * Pd + p) * 2;
    float off0 = g_off[q * Cd + j]     + b_off[j];
    float off1 = g_off[q * Cd + j + 1] + b_off[j + 1];
    int W0 = iss[l * 2], W1 = iss[l * 2 + 1];
    float ref0 = ref[(q * Ld + l) * 2];
    float ref1 = ref[(q * Ld + l) * 2 + 1];
    float loc0 = ref0 + off0 / (float)W1;
    float loc1 = ref1 + off1 / (float)W0;
    loc0 = fminf(fmaxf(loc0, 0.f), 0.999f);
    loc1 = fminf(fmaxf(loc1, 0.f), 0.999f);
    int ix = (int)(loc0 * (float)W0);
    int iy = (int)(loc1 * (float)W1);
    g_lin[id] = ix + iy * W0 + lsi[l];
}

// ---------------------------------------------------------------------------
// Fused softmax + key aggregation per (q,h)
// ---------------------------------------------------------------------------
__global__ void fuse_kernel(const float* __restrict__ flat)
{
    __shared__ float skeys[16][Cd];
    __shared__ int   slin[16];
    __shared__ float slog[16];
    __shared__ float sws[16];
    __shared__ float red[8];
    __shared__ float sm_max, sm_sum;

    const int q = blockIdx.x, h = blockIdx.y, t = threadIdx.x;
    const int warp = t >> 5, lane = t & 31;

    if (t < 16) {
        slin[t] = g_lin[(q * Hd + h) * 16 + t];
        slog[t] = g_slog[(q * Hd + h) * 16 + t];
    }
    __syncthreads();
#pragma unroll
    for (int k = 0; k < 16; k++)
        skeys[k][t] = flat[(long)slin[k] * Cd + t];

    const int row = (q * Hd + h) * LXd;
    float la0 = g_attn_a[row + t];
    float la1 = (t < LXd - 256) ? g_attn_a[row + 256 + t] : -1e30f;

    float m = fmaxf(la0, la1);
    if (t < 16) m = fmaxf(m, slog[t]);
#pragma unroll
    for (int o = 16; o > 0; o >>= 1) m = fmaxf(m, __shfl_xor_sync(0xffffffffu, m, o));
    if (lane == 0) red[warp] = m;
    __syncthreads();
    if (t == 0) {
        float mm = red[0];
        for (int w = 1; w < 8; w++) mm = fmaxf(mm, red[w]);
        sm_max = mm;
    }
    __syncthreads();
    m = sm_max;

    float e0 = expf(la0 - m);
    float e1 = (t < LXd - 256) ? expf(la1 - m) : 0.f;
    float es = (t < 16) ? expf(slog[t] - m) : 0.f;
    float csum = e0 + e1 + es;
#pragma unroll
    for (int o = 16; o > 0; o >>= 1) csum += __shfl_xor_sync(0xffffffffu, csum, o);
    if (lane == 0) red[warp] = csum;
    __syncthreads();
    if (t == 0) {
        float s2 = 0.f;
        for (int w = 0; w < 8; w++) s2 += red[w];
        sm_sum = s2;
    }
    __syncthreads();
    const float invZ = 1.f / sm_sum;

    g_attn_a[row + t] = e0 * invZ;
    if (t < LXd - 256) g_attn_a[row + 256 + t] = e1 * invZ;
    if (t < 16) sws[t] = es * invZ;
    if (warp == 0) {
        float ss = (t < 16) ? es * invZ : 0.f;
#pragma unroll
        for (int o = 16; o > 0; o >>= 1) ss += __shfl_xor_sync(0xffffffffu, ss, o);
        if (t == 0) g_ssum[q * Hd + h] = ss;
    }
    __syncthreads();

    float a = 0.f;
#pragma unroll
    for (int k = 0; k < 16; k++) a += sws[k] * skeys[k][t];
    g_agg[((long)q * Hd + h) * Cd + t] = a;
}

// out = q*headw_last + sum_h ssum*bv0f + 4 split-K partials
__global__ void combine_out(const float* __restrict__ query, float* __restrict__ out)
{
    int i = blockIdx.x * 256 + threadIdx.x;
    int c = i & 255, q = i >> 8;
    float v = query[i] * g_headw[Hd * Cd + c];
#pragma unroll
    for (int h = 0; h < Hd; h++) v += g_ssum[q * Hd + h] * g_bv0f[h * Cd + c];
    v += g_part[0][i] + g_part[1][i] + g_part[2][i] + g_part[3][i];
    out[i] = v;
}

// ---------------------------------------------------------------------------
extern "C" void kernel_launch(void* const* d_in, const int* in_sizes, int n_in,
                              void* d_out, int out_size)
{
    const float* query  = (const float*)d_in[0];
    const float* ref    = (const float*)d_in[1];
    const float* flat   = (const float*)d_in[2];
    const int*   iss    = (const int*)  d_in[3];
    const float* ak     = (const float*)d_in[4];
    const int*   lsi    = (const int*)  d_in[5];
    const float* W_off  = (const float*)d_in[6];
    const float* b_off  = (const float*)d_in[7];
    const float* W_attn = (const float*)d_in[8];
    const float* W_v    = (const float*)d_in[9];
    const float* b_v    = (const float*)d_in[10];
    const float* W_mix  = (const float*)d_in[11];
    float* out = (float*)d_out;

    float *p_off, *p_P, *p_attn_a, *p_agg, *p_v2f, *p_wv0ft, *p_part;
    cudaGetSymbolAddress((void**)&p_off,    g_off);
    cudaGetSymbolAddress((void**)&p_P,      g_P);
    cudaGetSymbolAddress((void**)&p_attn_a, g_attn_a);
    cudaGetSymbolAddress((void**)&p_agg,    g_agg);
    cudaGetSymbolAddress((void**)&p_v2f,    g_v2f);
    cudaGetSymbolAddress((void**)&p_wv0ft,  g_wv0ft);
    cudaGetSymbolAddress((void**)&p_part,   g_part);

    static int smem_set = 0;
    const int slog_smem = 64 * 268 * 4 + 2 * (64 * 40 * 2) + 2 * (32 * 264 * 2);
    if (!smem_set) {
        cudaFuncSetAttribute(slog_mma,
                             cudaFuncAttributeMaxDynamicSharedMemorySize, slog_smem);
        smem_set = 1;
    }

    // prep / folds
    prep_headw<<<1, 256>>>(W_mix, b_v);
    prep_fold<<<dim3(8, 8, Hd), dim3(32, 8)>>>(W_v);

    // raw v2[h] = ak @ Wv1[h]^T
    sgemm_tb<<<dim3((Cd + 63) / 64, (LXd + 63) / 64, Hd), 256>>>(
        ak, Cd, 0L, W_v + (long)Cd * Cd, Cd, 2L * Cd * Cd,
        p_v2f, Cd, (long)LXd * Cd, LXd, Cd, Cd);
    fold_v2f<<<Hd * LXd, 256>>>(b_v);

    // off = query @ W_off^T ; then sampling indices
    sgemm_tb<<<dim3(4, 32, 1), 256>>>(
        query, Cd, 0L, W_off, Cd, 0L, p_off, Cd, 0L, LQd, Cd, Cd);
    loc_kernel<<<(LQd * Hd * Ld * Pd + 255) / 256, 256>>>(ref, b_off, iss, lsi);

    // P[h] = Wadd[h] @ ak^T   (256 x 300, batched over h)
    sgemm_tb<<<dim3((LXd + 63) / 64, (Cd + 63) / 64, Hd), 256>>>(
        W_attn + 4L * Cd * Cd, Cd, 4L * Cd * Cd, ak, Cd, 0L,
        p_P, LXd, (long)Cd * LXd, Cd, LXd, Cd);

    // attn_a logits: query @ P[h]   (MMA)
    gemm_mma<<<dim3((LXd + 63) / 64, LQd / 64, Hd), 256>>>(
        query, Cd, 0L, p_P, LXd, (long)Cd * LXd,
        p_attn_a, Hd * LXd, (long)LXd, LQd, LXd, 0, Cd);

    // scrambled attn_s logits (MMA)
    slog_mma<<<dim3(32, Ld, Hd), 256, slog_smem>>>(flat, query, W_attn);

    // gather + softmax + aggregation
    fuse_kernel<<<dim3(LQd, Hd), 256>>>(flat);

    // output GEMMs, split-K into partial slabs (MMA)
    gemm_mma<<<dim3(4, 32, 1), 256>>>(
        p_agg, Hd * Cd, 0L, p_wv0ft, Cd, 0L,
        p_part + 0L * LQd * Cd, Cd, 0L, LQd, Cd, 0, 1024);
    gemm_mma<<<dim3(4, 32, 1), 256>>>(
        p_agg, Hd * Cd, 0L, p_wv0ft, Cd, 0L,
        p_part + 1L * LQd * Cd, Cd, 0L, LQd, Cd, 1024, 1024);
    gemm_mma<<<dim3(4, 32, 1), 256>>>(
        p_attn_a, Hd * LXd, 0L, p_v2f, Cd, 0L,
        p_part + 2L * LQd * Cd, Cd, 0L, LQd, Cd, 0, 1216);
    gemm_mma<<<dim3(4, 32, 1), 256>>>(
        p_attn_a, Hd * LXd, 0L, p_v2f, Cd, 0L,
        p_part + 3L * LQd * Cd, Cd, 0L, LQd, Cd, 1216, 1184);

    combine_out<<<LQd * Cd / 256, 256>>>(query, out);
}

// round 7
// speedup vs baseline: 1.8477x; 1.3281x over previous
#include <cuda_runtime.h>
#include <cuda_bf16.h>
#include <math.h>

// Problem constants
constexpr int Cd  = 256;
constexpr int Hd  = 8;
constexpr int Ld  = 4;
constexpr int Pd  = 4;
constexpr int LQd = 2048;
constexpr int LXd = 300;
constexpr int LEN = 5440;            // input_flatten rows
constexpr int PLD = 304;             // padded ld for P (bf16 rows)
constexpr int KAA = Hd * LXd;        // 2400

// ---------------------------------------------------------------------------
// Scratch (device globals; no allocation allowed)
// ---------------------------------------------------------------------------
__device__ __align__(16) float g_off[LQd * Cd];
__device__ __align__(16) int   g_lin[LQd * Hd * Ld * Pd];
__device__ __align__(16) float g_P[Hd * Cd * LXd];          // [h][c][x] fp32
__device__ __align__(16) float g_slog[LQd * Hd * 16];
__device__ __align__(16) float g_attn_a[LQd * KAA];         // logits fp32 [q][h*300+x]
__device__ __align__(16) float g_ssum[LQd * Hd];
__device__ __align__(16) float g_headw[(Hd + 1) * Cd];
__device__ __align__(16) float g_bv0f[Hd * Cd];
__device__ __align__(16) float g_v2f[Hd * LXd * Cd];        // fp32 raw v2
__device__ __align__(16) float g_part[4][LQd * Cd];

// bf16 hi/lo operand banks
__device__ __align__(16) __nv_bfloat16 g_qh[LQd * Cd],  g_ql[LQd * Cd];
__device__ __align__(16) __nv_bfloat16 g_fh[LEN * Cd],  g_fl[LEN * Cd];
__device__ __align__(16) __nv_bfloat16 g_Ph[Hd * Cd * PLD + 64], g_Pl[Hd * Cd * PLD + 64];
__device__ __align__(16) __nv_bfloat16 g_aah[LQd * KAA], g_aal[LQd * KAA];   // attn_a weights
__device__ __align__(16) __nv_bfloat16 g_aggh[LQd * Hd * Cd], g_aggl[LQd * Hd * Cd];
__device__ __align__(16) __nv_bfloat16 g_wv0h[Hd * Cd * Cd], g_wv0l[Hd * Cd * Cd]; // [h*256+e][c]
__device__ __align__(16) __nv_bfloat16 g_v2fh[Hd * LXd * Cd], g_v2fl[Hd * LXd * Cd]; // [h*300+x][c]

// ---------------------------------------------------------------------------
// MMA helpers
// ---------------------------------------------------------------------------
__device__ __forceinline__ unsigned smem_u32(const void* p) {
    return (unsigned)__cvta_generic_to_shared(p);
}
__device__ __forceinline__ void ldsm_x4(unsigned addr, unsigned& r0, unsigned& r1,
                                        unsigned& r2, unsigned& r3) {
    asm volatile("ldmatrix.sync.aligned.m8n8.x4.shared.b16 {%0,%1,%2,%3}, [%4];"
                 : "=r"(r0), "=r"(r1), "=r"(r2), "=r"(r3) : "r"(addr));
}
__device__ __forceinline__ void ldsm_x4_trans(unsigned addr, unsigned& r0, unsigned& r1,
                                              unsigned& r2, unsigned& r3) {
    asm volatile("ldmatrix.sync.aligned.m8n8.x4.trans.shared.b16 {%0,%1,%2,%3}, [%4];"
                 : "=r"(r0), "=r"(r1), "=r"(r2), "=r"(r3) : "r"(addr));
}
__device__ __forceinline__ void mma_bf16(float* c, const unsigned* a,
                                         unsigned b0, unsigned b1) {
    asm volatile(
        "mma.sync.aligned.m16n8k16.row.col.f32.bf16.bf16.f32 "
        "{%0,%1,%2,%3},{%4,%5,%6,%7},{%8,%9},{%0,%1,%2,%3};"
        : "+f"(c[0]), "+f"(c[1]), "+f"(c[2]), "+f"(c[3])
        : "r"(a[0]), "r"(a[1]), "r"(a[2]), "r"(a[3]), "r"(b0), "r"(b1));
}
__device__ __forceinline__ void split1(float f, __nv_bfloat16* h, __nv_bfloat16* l) {
    __nv_bfloat16 hh = __float2bfloat16(f);
    *h = hh;
    *l = __float2bfloat16(f - __bfloat162float(hh));
}

// ---------------------------------------------------------------------------
// bf16x3 GEMM core: C[128 x 64 tile] = A @ B, A/B pre-split hi/lo bf16.
// A row-major [.,lda], B row-major [K][ldb]. 256 thr, 8 warps (4m x 2n),
// warp tile 32x32. kLen % 32 == 0. M multiple of 128 (no row guard).
// ---------------------------------------------------------------------------
__device__ __forceinline__ void bf3_tile(
    const __nv_bfloat16* __restrict__ Ahg, const __nv_bfloat16* __restrict__ Alg, int lda,
    const __nv_bfloat16* __restrict__ Bhg, const __nv_bfloat16* __restrict__ Blg, int ldb,
    float* __restrict__ C, int ldc, int N, int kLen)
{
    extern __shared__ __nv_bfloat16 smb[];
    __nv_bfloat16* Ah = smb;               // [128][40]
    __nv_bfloat16* Al = Ah + 128 * 40;
    __nv_bfloat16* Bh = Al + 128 * 40;     // [32][72]
    __nv_bfloat16* Bl = Bh + 32 * 72;
    const int tid = threadIdx.x, lane = tid & 31, warp = tid >> 5;
    const int wm = warp >> 1, wn = warp & 1;
    const int rowBase = blockIdx.y * 128, colBase = blockIdx.x * 64;
    float acc[2][4][4] = {};

    for (int kt = 0; kt < kLen; kt += 32) {
#pragma unroll
        for (int i = 0; i < 2; i++) {
            int idx = tid + i * 256;
            int r = idx >> 2, q = idx & 3;
            long off = (long)(rowBase + r) * lda + kt + q * 8;
            *(uint4*)&Ah[r * 40 + q * 8] = *(const uint4*)&Ahg[off];
            *(uint4*)&Al[r * 40 + q * 8] = *(const uint4*)&Alg[off];
        }
        {
            int r = tid >> 3, q = tid & 7;
            long off = (long)(kt + r) * ldb + colBase + q * 8;
            *(uint4*)&Bh[r * 72 + q * 8] = *(const uint4*)&Bhg[off];
            *(uint4*)&Bl[r * 72 + q * 8] = *(const uint4*)&Blg[off];
        }
        __syncthreads();
#pragma unroll
        for (int kk = 0; kk < 32; kk += 16) {
            unsigned ah[2][4], al[2][4];
#pragma unroll
            for (int mi = 0; mi < 2; mi++) {
                int rr = wm * 32 + mi * 16 + (lane & 15);
                int cc = kk + (lane >> 4) * 8;
                ldsm_x4(smem_u32(&Ah[rr * 40 + cc]), ah[mi][0], ah[mi][1], ah[mi][2], ah[mi][3]);
                ldsm_x4(smem_u32(&Al[rr * 40 + cc]), al[mi][0], al[mi][1], al[mi][2], al[mi][3]);
            }
#pragma unroll
            for (int nb = 0; nb < 2; nb++) {
                unsigned bh[4], bl[4];
                int rr = kk + (lane & 15);
                int cc = wn * 32 + nb * 16 + (lane >> 4) * 8;
                ldsm_x4_trans(smem_u32(&Bh[rr * 72 + cc]), bh[0], bh[1], bh[2], bh[3]);
                ldsm_x4_trans(smem_u32(&Bl[rr * 72 + cc]), bl[0], bl[1], bl[2], bl[3]);
#pragma unroll
                for (int mi = 0; mi < 2; mi++)
#pragma unroll
                    for (int t = 0; t < 2; t++) {
                        int ni = nb * 2 + t;
                        mma_bf16(acc[mi][ni], ah[mi], bh[t * 2], bh[t * 2 + 1]);
                        mma_bf16(acc[mi][ni], ah[mi], bl[t * 2], bl[t * 2 + 1]);
                        mma_bf16(acc[mi][ni], al[mi], bh[t * 2], bh[t * 2 + 1]);
                    }
            }
        }
        __syncthreads();
    }
    const int g = lane >> 2, qp = lane & 3;
#pragma unroll
    for (int mi = 0; mi < 2; mi++)
#pragma unroll
        for (int ni = 0; ni < 4; ni++)
#pragma unroll
            for (int ch = 0; ch < 2; ch++) {
                int gr = rowBase + wm * 32 + mi * 16 + g + ch * 8;
                int gc = colBase + wn * 32 + ni * 8 + qp * 2;
                if (gc < N)
                    *(float2*)&C[(long)gr * ldc + gc] =
                        make_float2(acc[mi][ni][ch * 2], acc[mi][ni][ch * 2 + 1]);
            }
}

constexpr int BF3_SMEM = (128 * 40 + 32 * 72) * 2 * 2;  // 29696 bytes

// attn_a logits: query @ P[h]
__global__ __launch_bounds__(256) void attn_gemm()
{
    int h = blockIdx.z;
    bf3_tile(g_qh, g_ql, Cd,
             g_Ph + (long)h * Cd * PLD, g_Pl + (long)h * Cd * PLD, PLD,
             g_attn_a + h * LXd, KAA, LXd, Cd);
}

// output GEMM partial slabs (split-K, 4 slabs in one launch)
__global__ __launch_bounds__(256) void out_gemm()
{
    int z = blockIdx.z;
    const __nv_bfloat16 *Ahg, *Alg, *Bhg, *Blg;
    int lda, kOff, kLen;
    if (z < 2) {
        Ahg = g_aggh; Alg = g_aggl; Bhg = g_wv0h; Blg = g_wv0l;
        lda = Hd * Cd; kOff = z * 1024; kLen = 1024;
    } else {
        Ahg = g_aah;  Alg = g_aal;  Bhg = g_v2fh; Blg = g_v2fl;
        lda = KAA; kOff = (z - 2) * 1216; kLen = (z == 2) ? 1216 : 1184;
    }
    bf3_tile(Ahg + kOff, Alg + kOff, lda,
             Bhg + (long)kOff * Cd, Blg + (long)kOff * Cd, Cd,
             g_part[z], Cd, Cd, kLen);
}

// ---------------------------------------------------------------------------
// Scrambled attn_s logits via bf16x3 MMA, pre-split operands.
// Block (r,l,h): M[j,e] = sum_c' qf[r+32j,c'] * flat[slin[c']][e]  (64x256x256)
// then logit[p,j] = Ws[h,l,p*64+j,:] . M[j,:]
// ---------------------------------------------------------------------------
__global__ __launch_bounds__(256) void slog_mma(const float* __restrict__ W_attn)
{
    extern __shared__ char sm[];
    float* Ms = (float*)sm;                                  // [64][268] (overlays A/B)
    __nv_bfloat16* Ah = (__nv_bfloat16*)sm;                  // [64][40]
    __nv_bfloat16* Al = Ah + 64 * 40;
    __nv_bfloat16* Bh = Al + 64 * 40;                        // [32][264]
    __nv_bfloat16* Bl = Bh + 32 * 264;
    __shared__ int slin[256];

    const int r = blockIdx.x, l = blockIdx.y, h = blockIdx.z;
    const int tid = threadIdx.x, lane = tid & 31, warp = tid >> 5;
    const int wm = warp & 1, wn = warp >> 1;
    const int p2 = r >> 3, b = r & 7;
    slin[tid] = g_lin[((256 * b + tid) * Hd + h) * 16 + l * 4 + p2];
    __syncthreads();

    float acc[2][8][4] = {};

    for (int ck = 0; ck < 256; ck += 32) {
        {   // A: 64 rows x 32 cols hi/lo
            int j = tid >> 2, q = tid & 3;
            long off = (long)(r + 32 * j) * Cd + ck + q * 8;
            *(uint4*)&Ah[j * 40 + q * 8] = *(const uint4*)&g_qh[off];
            *(uint4*)&Al[j * 40 + q * 8] = *(const uint4*)&g_ql[off];
        }
#pragma unroll
        for (int i = 0; i < 4; i++) {    // B: 32 gathered rows x 256 cols hi/lo
            int idx = tid + i * 256;
            int kr = idx >> 5, q = idx & 31;
            long off = (long)slin[ck + kr] * Cd + q * 8;
            *(uint4*)&Bh[kr * 264 + q * 8] = *(const uint4*)&g_fh[off];
            *(uint4*)&Bl[kr * 264 + q * 8] = *(const uint4*)&g_fl[off];
        }
        __syncthreads();
#pragma unroll
        for (int kk = 0; kk < 32; kk += 16) {
            unsigned ah[2][4], al[2][4];
#pragma unroll
            for (int mi = 0; mi < 2; mi++) {
                int rr = wm * 32 + mi * 16 + (lane & 15);
                int cc = kk + (lane >> 4) * 8;
                ldsm_x4(smem_u32(&Ah[rr * 40 + cc]), ah[mi][0], ah[mi][1], ah[mi][2], ah[mi][3]);
                ldsm_x4(smem_u32(&Al[rr * 40 + cc]), al[mi][0], al[mi][1], al[mi][2], al[mi][3]);
            }
#pragma unroll
            for (int nb = 0; nb < 4; nb++) {
                unsigned bh[4], bl[4];
                int rr = kk + (lane & 15);
                int cc = wn * 64 + nb * 16 + (lane >> 4) * 8;
                ldsm_x4_trans(smem_u32(&Bh[rr * 264 + cc]), bh[0], bh[1], bh[2], bh[3]);
                ldsm_x4_trans(smem_u32(&Bl[rr * 264 + cc]), bl[0], bl[1], bl[2], bl[3]);
#pragma unroll
                for (int mi = 0; mi < 2; mi++)
#pragma unroll
                    for (int t = 0; t < 2; t++) {
                        int ni = nb * 2 + t;
                        mma_bf16(acc[mi][ni], ah[mi], bh[t * 2], bh[t * 2 + 1]);
                        mma_bf16(acc[mi][ni], ah[mi], bl[t * 2], bl[t * 2 + 1]);
                        mma_bf16(acc[mi][ni], al[mi], bh[t * 2], bh[t * 2 + 1]);
                    }
            }
        }
        __syncthreads();
    }

    // acc -> Ms (overlays A/B; safe after the loop's trailing barrier)
    const int g = lane >> 2, qp = lane & 3;
#pragma unroll
    for (int mi = 0; mi < 2; mi++)
#pragma unroll
        for (int ni = 0; ni < 8; ni++)
#pragma unroll
            for (int ch = 0; ch < 2; ch++) {
                int row = wm * 32 + mi * 16 + g + ch * 8;
                int col = wn * 64 + ni * 8 + qp * 2;
                *(float2*)&Ms[row * 268 + col] =
                    make_float2(acc[mi][ni][ch * 2], acc[mi][ni][ch * 2 + 1]);
            }
    __syncthreads();

    // stage 2: one logit per thread
    int p = tid >> 6, j = tid & 63;
    int cstar = p * 64 + j;
    const float4* w4 = (const float4*)(W_attn + ((long)(h * Ld + l) * Cd + cstar) * Cd);
    const float* mrow = Ms + j * 268;
    float s = 0.f;
#pragma unroll 4
    for (int e4 = 0; e4 < 64; e4++) {
        float4 w = w4[e4];
        s += w.x * mrow[e4 * 4] + w.y * mrow[e4 * 4 + 1]
           + w.z * mrow[e4 * 4 + 2] + w.w * mrow[e4 * 4 + 3];
    }
    int q = r + 32 * j;
    g_slog[(q * Hd + h) * 16 + l * 4 + p] = s;
}
constexpr int SLOG_SMEM = 64 * 268 * 4;   // 68608 (>= overlaid A/B 44032)

// ---------------------------------------------------------------------------
// fp32 tiled GEMM (TB): C = A @ B^T (small prep GEMMs)
// ---------------------------------------------------------------------------
__global__ void sgemm_tb(const float* __restrict__ A, int lda, long sA,
                         const float* __restrict__ B, int ldb, long sB,
                         float* __restrict__ Cm, int ldc, long sC,
                         int M, int N, int K)
{
    __shared__ float As[16][68];
    __shared__ float Bs[16][68];
    const int tid = threadIdx.x;
    A  += (long)blockIdx.z * sA;
    B  += (long)blockIdx.z * sB;
    Cm += (long)blockIdx.z * sC;
    const int rowBase = blockIdx.y * 64, colBase = blockIdx.x * 64;
    const int tr = (tid >> 4) * 4, tc = (tid & 15) * 4;
    float acc[4][4] = {};

    for (int kt = 0; kt < K; kt += 16) {
#pragma unroll
        for (int i = 0; i < 4; i++) {
            int idx = tid + i * 256;
            int ar = idx >> 4, ac = idx & 15;
            int gr = rowBase + ar;
            As[ac][ar] = (gr < M) ? A[(long)gr * lda + kt + ac] : 0.f;
        }
#pragma unroll
        for (int i = 0; i < 4; i++) {
            int idx = tid + i * 256;
            int bn = idx >> 4, bk = idx & 15;
            int gn = colBase + bn;
            Bs[bk][bn] = (gn < N) ? B[(long)gn * ldb + kt + bk] : 0.f;
        }
        __syncthreads();
#pragma unroll
        for (int k = 0; k < 16; k++) {
            float4 av = *(const float4*)&As[k][tr];
            float4 bv = *(const float4*)&Bs[k][tc];
            float a[4] = {av.x, av.y, av.z, av.w};
            float b[4] = {bv.x, bv.y, bv.z, bv.w};
#pragma unroll
            for (int i = 0; i < 4; i++)
#pragma unroll
                for (int j = 0; j < 4; j++) acc[i][j] += a[i] * b[j];
        }
        __syncthreads();
    }
#pragma unroll
    for (int i = 0; i < 4; i++) {
        int gr = rowBase + tr + i;
        if (gr >= M) continue;
#pragma unroll
        for (int j = 0; j < 4; j++) {
            int gc = colBase + tc + j;
            if (gc < N) Cm[(long)gr * ldc + gc] = acc[i][j];
        }
    }
}

// ---------------------------------------------------------------------------
// Conversion / prep kernels
// ---------------------------------------------------------------------------
__global__ void cvt_qf(const float* __restrict__ query, const float* __restrict__ flat)
{
    long i = (long)blockIdx.x * 256 + threadIdx.x;
    if (i < (long)LQd * Cd) {
        split1(query[i], &g_qh[i], &g_ql[i]);
    } else {
        long j = i - (long)LQd * Cd;
        split1(flat[j], &g_fh[j], &g_fl[j]);
    }
}

__global__ void cvt_P()
{
    int i = blockIdx.x * 256 + threadIdx.x;   // < 8*256*300
    int hc = i / LXd, x = i - hc * LXd;
    split1(g_P[i], &g_Ph[(long)hc * PLD + x], &g_Pl[(long)hc * PLD + x]);
}

__global__ void prep_headw(const float* __restrict__ W_mix, const float* __restrict__ b_v)
{
    int c = threadIdx.x;
    float m = -1e30f;
    for (int j = 0; j <= Hd; j++) m = fmaxf(m, W_mix[c * (Hd + 1) + j]);
    float e[Hd + 1];
    float Z = 0.f;
    for (int j = 0; j <= Hd; j++) { e[j] = expf(W_mix[c * (Hd + 1) + j] - m); Z += e[j]; }
    float invZ = 1.f / Z;
    for (int j = 0; j <= Hd; j++) g_headw[j * Cd + c] = e[j] * invZ;
    for (int h = 0; h < Hd; h++)  g_bv0f[h * Cd + c] = e[h] * invZ * b_v[(2 * h) * Cd + c];
}

// wv0ft[h][e][c] = head_w[h][c] * W_v[2h][c][e]  -> bf16 hi/lo
__global__ void prep_fold(const float* __restrict__ W_v)
{
    __shared__ float t[32][33];
    int h = blockIdx.z;
    int e0 = blockIdx.x * 32, c0 = blockIdx.y * 32;
    int x = threadIdx.x, y = threadIdx.y;
    for (int i = 0; i < 32; i += 8) {
        int cc = c0 + y + i;
        t[y + i][x] = W_v[((long)(2 * h) * Cd + cc) * Cd + e0 + x];
    }
    __syncthreads();
    for (int i = 0; i < 32; i += 8) {
        int ee = e0 + y + i;
        int cc = c0 + x;
        float v = g_headw[h * Cd + cc] * t[x][y + i];
        long o = ((long)h * Cd + ee) * Cd + cc;
        split1(v, &g_wv0h[o], &g_wv0l[o]);
    }
}

// v2f[h][x][c] = head_w[h][c]*(v2_raw + b) -> bf16 hi/lo
__global__ void fold_v2f(const float* __restrict__ b_v)
{
    int i = blockIdx.x * 256 + threadIdx.x;
    int c = i & 255;
    int h = (i >> 8) / LXd;
    float v = g_headw[h * Cd + c] * (g_v2f[i] + b_v[(2 * h + 1) * Cd + c]);
    split1(v, &g_v2fh[i], &g_v2fl[i]);
}

__global__ void loc_kernel(const float* __restrict__ ref, const float* __restrict__ b_off,
                           const int* __restrict__ iss, const int* __restrict__ lsi)
{
    int id = blockIdx.x * 256 + threadIdx.x;
    if (id >= LQd * Hd * Ld * Pd) return;
    int q = id >> 7;
    int r = id & 127;
    int hh = r >> 4;
    int l = (r >> 2) & 3;
    int p = r & 3;
    int j = ((hh * Ld + l) * Pd + p) * 2;
    float off0 = g_off[q * Cd + j]     + b_off[j];
    float off1 = g_off[q * Cd + j + 1] + b_off[j + 1];
    int W0 = iss[l * 2], W1 = iss[l * 2 + 1];
    float ref0 = ref[(q * Ld + l) * 2];
    float ref1 = ref[(q * Ld + l) * 2 + 1];
    float loc0 = ref0 + off0 / (float)W1;
    float loc1 = ref1 + off1 / (float)W0;
    loc0 = fminf(fmaxf(loc0, 0.f), 0.999f);
    loc1 = fminf(fmaxf(loc1, 0.f), 0.999f);
    int ix = (int)(loc0 * (float)W0);
    int iy = (int)(loc1 * (float)W1);
    g_lin[id] = ix + iy * W0 + lsi[l];
}

// ---------------------------------------------------------------------------
// Fused softmax + key aggregation per (q,h); emits bf16 hi/lo operands.
// ---------------------------------------------------------------------------
__global__ void fuse_kernel(const float* __restrict__ flat)
{
    __shared__ float skeys[16][Cd];
    __shared__ int   slin[16];
    __shared__ float slog[16];
    __shared__ float sws[16];
    __shared__ float red[8];
    __shared__ float sm_max, sm_sum;

    const int q = blockIdx.x, h = blockIdx.y, t = threadIdx.x;
    const int warp = t >> 5, lane = t & 31;

    if (t < 16) {
        slin[t] = g_lin[(q * Hd + h) * 16 + t];
        slog[t] = g_slog[(q * Hd + h) * 16 + t];
    }
    __syncthreads();
#pragma unroll
    for (int k = 0; k < 16; k++)
        skeys[k][t] = flat[(long)slin[k] * Cd + t];

    const long row = (long)(q * Hd + h) * LXd;
    float la0 = g_attn_a[(long)q * KAA + h * LXd + t];
    float la1 = (t < LXd - 256) ? g_attn_a[(long)q * KAA + h * LXd + 256 + t] : -1e30f;

    float m = fmaxf(la0, la1);
    if (t < 16) m = fmaxf(m, slog[t]);
#pragma unroll
    for (int o = 16; o > 0; o >>= 1) m = fmaxf(m, __shfl_xor_sync(0xffffffffu, m, o));
    if (lane == 0) red[warp] = m;
    __syncthreads();
    if (t == 0) {
        float mm = red[0];
        for (int w = 1; w < 8; w++) mm = fmaxf(mm, red[w]);
        sm_max = mm;
    }
    __syncthreads();
    m = sm_max;

    float e0 = expf(la0 - m);
    float e1 = (t < LXd - 256) ? expf(la1 - m) : 0.f;
    float es = (t < 16) ? expf(slog[t] - m) : 0.f;
    float csum = e0 + e1 + es;
#pragma unroll
    for (int o = 16; o > 0; o >>= 1) csum += __shfl_xor_sync(0xffffffffu, csum, o);
    if (lane == 0) red[warp] = csum;
    __syncthreads();
    if (t == 0) {
        float s2 = 0.f;
        for (int w = 0; w < 8; w++) s2 += red[w];
        sm_sum = s2;
    }
    __syncthreads();
    const float invZ = 1.f / sm_sum;

    {   // attn_a weights -> bf16 hi/lo, layout [q][h*300+x]
        long o = (long)q * KAA + h * LXd + t;
        split1(e0 * invZ, &g_aah[o], &g_aal[o]);
        if (t < LXd - 256) split1(e1 * invZ, &g_aah[o + 256], &g_aal[o + 256]);
    }
    if (t < 16) sws[t] = es * invZ;
    if (warp == 0) {
        float ss = (t < 16) ? es * invZ : 0.f;
#pragma unroll
        for (int o = 16; o > 0; o >>= 1) ss += __shfl_xor_sync(0xffffffffu, ss, o);
        if (t == 0) g_ssum[q * Hd + h] = ss;
    }
    __syncthreads();

    float a = 0.f;
#pragma unroll
    for (int k = 0; k < 16; k++) a += sws[k] * skeys[k][t];
    long o = (long)(q * Hd + h) * Cd + t;
    split1(a, &g_aggh[o], &g_aggl[o]);
    (void)row;
}

// out = q*headw_last + sum_h ssum*bv0f + 4 split-K partials
__global__ void combine_out(const float* __restrict__ query, float* __restrict__ out)
{
    int i = blockIdx.x * 256 + threadIdx.x;
    int c = i & 255, q = i >> 8;
    float v = query[i] * g_headw[Hd * Cd + c];
#pragma unroll
    for (int h = 0; h < Hd; h++) v += g_ssum[q * Hd + h] * g_bv0f[h * Cd + c];
    v += g_part[0][i] + g_part[1][i] + g_part[2][i] + g_part[3][i];
    out[i] = v;
}

// ---------------------------------------------------------------------------
extern "C" void kernel_launch(void* const* d_in, const int* in_sizes, int n_in,
                              void* d_out, int out_size)
{
    const float* query  = (const float*)d_in[0];
    const float* ref    = (const float*)d_in[1];
    const float* flat   = (const float*)d_in[2];
    const int*   iss    = (const int*)  d_in[3];
    const float* ak     = (const float*)d_in[4];
    const int*   lsi    = (const int*)  d_in[5];
    const float* W_off  = (const float*)d_in[6];
    const float* b_off  = (const float*)d_in[7];
    const float* W_attn = (const float*)d_in[8];
    const float* W_v    = (const float*)d_in[9];
    const float* b_v    = (const float*)d_in[10];
    const float* W_mix  = (const float*)d_in[11];
    float* out = (float*)d_out;

    float *p_off, *p_P, *p_v2f;
    cudaGetSymbolAddress((void**)&p_off, g_off);
    cudaGetSymbolAddress((void**)&p_P,   g_P);
    cudaGetSymbolAddress((void**)&p_v2f, g_v2f);

    static int smem_set = 0;
    if (!smem_set) {
        cudaFuncSetAttribute(slog_mma,
                             cudaFuncAttributeMaxDynamicSharedMemorySize, SLOG_SMEM);
        smem_set = 1;
    }

    // operand conversion (query + flat)
    cvt_qf<<<(LQd * Cd + LEN * Cd) / 256, 256>>>(query, flat);

    // off = query @ W_off^T ; sampling indices
    sgemm_tb<<<dim3(4, 32, 1), 256>>>(
        query, Cd, 0L, W_off, Cd, 0L, p_off, Cd, 0L, LQd, Cd, Cd);
    loc_kernel<<<(LQd * Hd * Ld * Pd + 255) / 256, 256>>>(ref, b_off, iss, lsi);

    // P[h] = Wadd[h] @ ak^T, then hi/lo split
    sgemm_tb<<<dim3((LXd + 63) / 64, (Cd + 63) / 64, Hd), 256>>>(
        W_attn + 4L * Cd * Cd, Cd, 4L * Cd * Cd, ak, Cd, 0L,
        p_P, LXd, (long)Cd * LXd, Cd, LXd, Cd);
    cvt_P<<<Hd * Cd * LXd / 256, 256>>>();

    // attn_a logits: query @ P[h]   (bf16x3 MMA)
    attn_gemm<<<dim3((LXd + 63) / 64, LQd / 128, Hd), 256, BF3_SMEM>>>();

    // scrambled attn_s logits (bf16x3 MMA)
    slog_mma<<<dim3(32, Ld, Hd), 256, SLOG_SMEM>>>(W_attn);

    // head mixing + value-side folds (independent prep)
    prep_headw<<<1, 256>>>(W_mix, b_v);
    sgemm_tb<<<dim3((Cd + 63) / 64, (LXd + 63) / 64, Hd), 256>>>(
        ak, Cd, 0L, W_v + (long)Cd * Cd, Cd, 2L * Cd * Cd,
        p_v2f, Cd, (long)LXd * Cd, LXd, Cd, Cd);
    fold_v2f<<<Hd * LXd, 256>>>(b_v);
    prep_fold<<<dim3(8, 8, Hd), dim3(32, 8)>>>(W_v);

    // gather + softmax + aggregation (emits bf16 hi/lo A-operands)
    fuse_kernel<<<dim3(LQd, Hd), 256>>>(flat);

    // output GEMMs: 4 split-K slabs in ONE launch
    out_gemm<<<dim3(Cd / 64, LQd / 128, 4), 256, BF3_SMEM>>>();

    combine_out<<<LQd * Cd / 256, 256>>>(query, out);
}